// round 10
// baseline (speedup 1.0000x reference)
#include <cuda_runtime.h>
#include <cuda_fp16.h>
#include <math.h>

// Problem constants (fixed by the dataset)
#define NB 256      // batch (docs)
#define NL 512      // tokens per doc
#define ND 1024     // embedding dim
#define NV 50001    // emb_table rows
// emb_table is (V+1, D) = (50001, 1024) float32

// Scratch (device globals — no allocation allowed)
__device__ float g_hpart[NB * 4 * ND];   // per-doc 4 partials (part x row-parity)
__device__ float g_v[NB * ND];           // v[b] = W_b @ mean(emb[b])
__device__ uint2 g_ef[(size_t)NV * 256]; // fp16 table: 2048 B/row (256 uint2)

__device__ __forceinline__ unsigned h2_bits(__half2 h) {
    unsigned u;
    memcpy(&u, &h, 4);
    return u;
}
__device__ __forceinline__ float2 bits_to_f2(unsigned u) {
    __half2 h;
    memcpy(&h, &u, 4);
    return __half22float2(h);
}

// ---------------------------------------------------------------------------
// Kernel 0: streaming fp32 -> fp16 convert of the whole table (coalesced).
// 205 MB read + 102 MB write; result fits in L2 (102 MB < 126 MB).
// ---------------------------------------------------------------------------
__global__ void k_convert(const float* __restrict__ emb) {
    const float4* src = reinterpret_cast<const float4*>(emb);
    const size_t n = (size_t)NV * 256;
    size_t i = (size_t)blockIdx.x * blockDim.x + threadIdx.x;
    const size_t stride = (size_t)gridDim.x * blockDim.x;
    for (; i < n; i += stride) {
        float4 v = __ldg(&src[i]);
        uint2 o;
        o.x = h2_bits(__floats2half2_rn(v.x, v.y));
        o.y = h2_bits(__floats2half2_rn(v.z, v.w));
        g_ef[i] = o;
    }
}

// ---------------------------------------------------------------------------
// Pass 1: partial sums of gathered fp16 rows, wide loads.
// 512 CTAs (2/doc), 256 threads. Each iteration covers TWO rows: threads
// 0..127 take the even row, 128..255 the odd row; each thread loads one
// uint4 (8 halves). 128 iterations -> load count halved vs R9.
// Emits partial (b, part, sub): sub = row parity group.
// ---------------------------------------------------------------------------
__global__ void k_hidden(const int* __restrict__ tokens) {
    __shared__ int s_tok[256];
    const int b    = blockIdx.x >> 1;
    const int part = blockIdx.x & 1;
    const int t    = threadIdx.x;

    s_tok[t] = tokens[b * NL + part * 256 + t] + 1;   // +1 per reference lookup
    __syncthreads();

    const uint4* ef4 = reinterpret_cast<const uint4*>(g_ef);
    const int sub = t >> 7;      // 0: even rows, 1: odd rows
    const int c   = t & 127;     // uint4 chunk within row (8 halves)

    float4 acc0 = make_float4(0.f, 0.f, 0.f, 0.f);
    float4 acc1 = make_float4(0.f, 0.f, 0.f, 0.f);

#pragma unroll 4
    for (int l = 0; l < 256; l += 2) {
        const int row = s_tok[l + sub];
        uint4 q = __ldg(&ef4[(size_t)row * 128 + c]);
        float2 f0 = bits_to_f2(q.x);
        float2 f1 = bits_to_f2(q.y);
        float2 f2 = bits_to_f2(q.z);
        float2 f3 = bits_to_f2(q.w);
        acc0.x += f0.x; acc0.y += f0.y; acc0.z += f1.x; acc0.w += f1.y;
        acc1.x += f2.x; acc1.y += f2.y; acc1.z += f3.x; acc1.w += f3.y;
    }

    // partial index: b*4 + part*2 + sub ; this thread owns d = c*8 .. c*8+7
    float4* hp4 = reinterpret_cast<float4*>(g_hpart);
    const int pidx = (b * 2 + part) * 2 + sub;
    hp4[(size_t)pidx * 256 + c * 2 + 0] = acc0;
    hp4[(size_t)pidx * 256 + c * 2 + 1] = acc1;
}

// ---------------------------------------------------------------------------
// Small GEMM: v[b,n] = sum_e hidden[b,e] * W[n,e], hidden = (4 partials)/512.
// M=256, N=1024, K=1024. BM=32, BN=64, BK=32; 256 threads; 2x4 microtile.
// ---------------------------------------------------------------------------
__global__ void k_v(const float* __restrict__ W) {
    __shared__ float sA[32 * 34];   // [k][m], pad to 34
    __shared__ float sB[32 * 68];   // [k][n], pad to 68

    const int tid = threadIdx.x;
    const int bn0 = blockIdx.x * 64;
    const int bm0 = blockIdx.y * 32;
    const int tx  = tid & 15;
    const int ty  = tid >> 4;
    const int lm  = tid >> 3;
    const int lk  = tid & 7;

    const float4* W4  = reinterpret_cast<const float4*>(W);
    const float4* hp4 = reinterpret_cast<const float4*>(g_hpart);

    float acc[2][4] = {{0.f,0.f,0.f,0.f},{0.f,0.f,0.f,0.f}};

    for (int k0 = 0; k0 < 1024; k0 += 32) {
        {
            const int bb = bm0 + lm;
            const int f  = (k0 >> 2) + lk;
            float4 h0 = hp4[(size_t)(bb * 4 + 0) * 256 + f];
            float4 h1 = hp4[(size_t)(bb * 4 + 1) * 256 + f];
            float4 h2 = hp4[(size_t)(bb * 4 + 2) * 256 + f];
            float4 h3 = hp4[(size_t)(bb * 4 + 3) * 256 + f];
            const float s = 1.0f / 512.0f;
            sA[(lk * 4 + 0) * 34 + lm] = (h0.x + h1.x + h2.x + h3.x) * s;
            sA[(lk * 4 + 1) * 34 + lm] = (h0.y + h1.y + h2.y + h3.y) * s;
            sA[(lk * 4 + 2) * 34 + lm] = (h0.z + h1.z + h2.z + h3.z) * s;
            sA[(lk * 4 + 3) * 34 + lm] = (h0.w + h1.w + h2.w + h3.w) * s;
        }
#pragma unroll
        for (int r = 0; r < 2; ++r) {
            const int n = lm + r * 32;
            float4 w = W4[(size_t)(bn0 + n) * 256 + (k0 >> 2) + lk];
            sB[(lk * 4 + 0) * 68 + n] = w.x;
            sB[(lk * 4 + 1) * 68 + n] = w.y;
            sB[(lk * 4 + 2) * 68 + n] = w.z;
            sB[(lk * 4 + 3) * 68 + n] = w.w;
        }
        __syncthreads();

#pragma unroll
        for (int k = 0; k < 32; ++k) {
            float2 a2 = *reinterpret_cast<const float2*>(&sA[k * 34 + ty * 2]);
            float4 b4 = *reinterpret_cast<const float4*>(&sB[k * 68 + tx * 4]);
            acc[0][0] += a2.x * b4.x; acc[0][1] += a2.x * b4.y;
            acc[0][2] += a2.x * b4.z; acc[0][3] += a2.x * b4.w;
            acc[1][0] += a2.y * b4.x; acc[1][1] += a2.y * b4.y;
            acc[1][2] += a2.y * b4.z; acc[1][3] += a2.y * b4.w;
        }
        __syncthreads();
    }

#pragma unroll
    for (int i = 0; i < 2; ++i) {
        const int row = bm0 + ty * 2 + i;
        float4 o = make_float4(acc[i][0], acc[i][1], acc[i][2], acc[i][3]);
        reinterpret_cast<float4*>(g_v)[row * 256 + (bn0 >> 2) + tx] = o;
    }
}

// ---------------------------------------------------------------------------
// Pass 2: split-D warp pairs reading fp16 table with 2x LDG.128 per token.
// 1 CTA/doc, 512 thr = 8 pairs; pair p: tokens p*64..+63; half h owns
// D-components h*512..+511. Lane owns d = h*512 + it*256 + lane*8 .. +7.
// 2 CTAs/SM -> 256 CTAs in one wave, 32 warps/SM.
// ---------------------------------------------------------------------------
__global__ void __launch_bounds__(512, 2)
k_ct(const int* __restrict__ tokens, float* __restrict__ out) {
    __shared__ int   s_tok[512];
    __shared__ float s_ct[1024];
    __shared__ float s_ex[8][2][2];   // [pair][token parity][half]
    __shared__ float s_m[8];
    __shared__ float s_d[8];

    const int b    = blockIdx.x;
    const int tid  = threadIdx.x;
    const int w    = tid >> 5;
    const int p    = w >> 1;          // pair 0..7
    const int h    = w & 1;           // D-half 0/1
    const int lane = tid & 31;

    s_tok[tid]      = tokens[b * NL + tid] + 1;
    s_ct[tid]       = 0.f;
    s_ct[tid + 512] = 0.f;
    __syncthreads();

    const float4* v4   = reinterpret_cast<const float4*>(g_v);
    const uint4*  ef4  = reinterpret_cast<const uint4*>(g_ef);
    const uint4*  base = ef4 + h * 64 + lane;   // half-row base + lane offset

    // lane owns d = h*512 + it*256 + lane*8 .. +7, it = 0..1
    // vr[it][k]: float4 at v index (h*512 + it*256 + lane*8)/4 + k
    float4 vr[2][2];
#pragma unroll
    for (int it = 0; it < 2; ++it) {
        vr[it][0] = v4[b * 256 + h * 128 + it * 64 + lane * 2 + 0];
        vr[it][1] = v4[b * 256 + h * 128 + it * 64 + lane * 2 + 1];
    }

    float4 nacc[2][2];
#pragma unroll
    for (int it = 0; it < 2; ++it) {
        nacc[it][0] = make_float4(0.f, 0.f, 0.f, 0.f);
        nacc[it][1] = make_float4(0.f, 0.f, 0.f, 0.f);
    }

    float m   = -INFINITY;
    float den = 0.f;

    for (int j = 0; j < 64; ++j) {
        const int row = s_tok[p * 64 + j];
        const uint4* q = base + (size_t)row * 128;

        // 2 independent LDG.128 (16 halves)
        uint4 r0 = __ldg(&q[0]);
        uint4 r1 = __ldg(&q[32]);

        float4 e[2][2];
        {
            float2 a = bits_to_f2(r0.x), b2 = bits_to_f2(r0.y);
            float2 c = bits_to_f2(r0.z), d  = bits_to_f2(r0.w);
            e[0][0] = make_float4(a.x, a.y, b2.x, b2.y);
            e[0][1] = make_float4(c.x, c.y, d.x, d.y);
            a = bits_to_f2(r1.x); b2 = bits_to_f2(r1.y);
            c = bits_to_f2(r1.z); d  = bits_to_f2(r1.w);
            e[1][0] = make_float4(a.x, a.y, b2.x, b2.y);
            e[1][1] = make_float4(c.x, c.y, d.x, d.y);
        }

        float s = 0.f;
#pragma unroll
        for (int it = 0; it < 2; ++it)
#pragma unroll
            for (int k = 0; k < 2; ++k)
                s += e[it][k].x * vr[it][k].x + e[it][k].y * vr[it][k].y
                   + e[it][k].z * vr[it][k].z + e[it][k].w * vr[it][k].w;
#pragma unroll
        for (int o = 16; o; o >>= 1) s += __shfl_xor_sync(0xffffffffu, s, o);

        if (lane == 0) s_ex[p][j & 1][h] = s;
        asm volatile("bar.sync %0, 64;" :: "r"(p + 1) : "memory");
        s = s_ex[p][j & 1][0] + s_ex[p][j & 1][1];

        const float m_new = fmaxf(m, s);
        const float c  = __expf(m - m_new);   // 1 when max unchanged, 0 on first
        const float wl = __expf(s - m_new);
        den = den * c + wl;
        if (c != 1.0f) {
#pragma unroll
            for (int it = 0; it < 2; ++it)
#pragma unroll
                for (int k = 0; k < 2; ++k) {
                    nacc[it][k].x *= c; nacc[it][k].y *= c;
                    nacc[it][k].z *= c; nacc[it][k].w *= c;
                }
        }
#pragma unroll
        for (int it = 0; it < 2; ++it)
#pragma unroll
            for (int k = 0; k < 2; ++k) {
                nacc[it][k].x += wl * e[it][k].x; nacc[it][k].y += wl * e[it][k].y;
                nacc[it][k].z += wl * e[it][k].z; nacc[it][k].w += wl * e[it][k].w;
            }
        m = m_new;
    }

    // per-pair state (identical in both halves of a pair)
    if (h == 0 && lane == 0) { s_m[p] = m; s_d[p] = den; }
    __syncthreads();

    float M = -INFINITY;
#pragma unroll
    for (int i = 0; i < 8; ++i) M = fmaxf(M, s_m[i]);
    float dg = 0.f;
#pragma unroll
    for (int i = 0; i < 8; ++i) dg += s_d[i] * __expf(s_m[i] - M);

    const float sc = __expf(m - M) / dg;
#pragma unroll
    for (int it = 0; it < 2; ++it)
#pragma unroll
        for (int k = 0; k < 2; ++k) {
            const int d0 = h * 512 + it * 256 + lane * 8 + k * 4;
            atomicAdd(&s_ct[d0 + 0], nacc[it][k].x * sc);
            atomicAdd(&s_ct[d0 + 1], nacc[it][k].y * sc);
            atomicAdd(&s_ct[d0 + 2], nacc[it][k].z * sc);
            atomicAdd(&s_ct[d0 + 3], nacc[it][k].w * sc);
        }
    __syncthreads();

    out[b * ND + tid]       = s_ct[tid];
    out[b * ND + tid + 512] = s_ct[tid + 512];
}

// ---------------------------------------------------------------------------
extern "C" void kernel_launch(void* const* d_in, const int* in_sizes, int n_in,
                              void* d_out, int out_size) {
    const int*   tokens = (const int*)d_in[0];
    // d_in[1] = max_len (scalar, unused — fixed at 512)
    const float* emb    = (const float*)d_in[2];
    const float* W      = (const float*)d_in[3];
    float*       out    = (float*)d_out;

    k_convert<<<2048, 256>>>(emb);
    k_hidden<<<NB * 2, 256>>>(tokens);
    k_v<<<dim3(16, 8), 256>>>(W);
    k_ct<<<NB, 512>>>(tokens, out);
}